// round 4
// baseline (speedup 1.0000x reference)
#include <cuda_runtime.h>
#include <cuda_bf16.h>

// DepthwiseRREUp: x [B=8, C=256, G=4, H=64, W=64] fp32, dw [C,1,2,2] fp32.
// out [B, C, G, 128, 128]:
//   out[b,c,g,2i+di,2j+dj] = x[b,c,g,i,j] * f(c,g)[di,dj],  f = rot90(dw[c], k=g) CCW.
//
// dw[c] = [[a,b],[c,d]]:
//   g=0: [[a,b],[c,d]]   g=1: [[b,d],[a,c]]   g=2: [[d,c],[b,a]]   g=3: [[c,a],[d,b]]
//
// One thread per input float2 x 2 ROWS (rows 2r and 2r+1, same 2 columns).
// Each thread: 2 independent LDG.64 (warp-contiguous, MLP=2) and 4 STG.128,
// each store fully lane-contiguous (consecutive lanes -> consecutive float4).

#define F2_PER_ROW   32              // 64/2 input float2 per row
#define F2_PER_PLANE 2048            // 64*64/2
#define OUT_PLANE_F4 4096            // 128*128/4
#define OUT_ROW_F4   32              // 128/4

__global__ __launch_bounds__(256)
void rre_up_kernel(const float2* __restrict__ x2,
                   const float4* __restrict__ dw4,   // [C] float4 = (a,b,c,d)
                   float4* __restrict__ out,
                   int nthreads)
{
    int t = blockIdx.x * blockDim.x + threadIdx.x;
    if (t >= nthreads) return;

    int plane = t >> 10;             // (b*C + c)*G + g, 0..8191  (1024 threads/plane)
    int p     = t & 1023;            // within-plane: 32 row-pairs x 32 cols
    int rp    = p >> 5;              // row pair 0..31 -> input rows 2rp, 2rp+1
    int j2    = p & 31;              // input float2 col == output float4 col

    int cg = plane & (256 * 4 - 1);  // c*4 + g
    int c  = cg >> 2;
    int g  = cg & 3;

    float4 w = __ldg(&dw4[c]);       // (a,b,c,d); 4KB total, broadcast via RO path

    float f00, f01, f10, f11;
    switch (g) {
        case 0: f00 = w.x; f01 = w.y; f10 = w.z; f11 = w.w; break;
        case 1: f00 = w.y; f01 = w.w; f10 = w.x; f11 = w.z; break;
        case 2: f00 = w.w; f01 = w.z; f10 = w.y; f11 = w.x; break;
        default:f00 = w.z; f01 = w.x; f10 = w.w; f11 = w.y; break;
    }

    const float2* xin = x2 + (size_t)plane * F2_PER_PLANE
                           + (size_t)(2 * rp) * F2_PER_ROW + j2;
    // Two independent streamed loads (rows 2rp and 2rp+1)
    float2 v0 = __ldcs(&xin[0]);
    float2 v1 = __ldcs(&xin[F2_PER_ROW]);

    float4* o = out + (size_t)plane * OUT_PLANE_F4
                    + (size_t)(4 * rp) * OUT_ROW_F4
                    + j2;

    float4 r0 = make_float4(v0.x * f00, v0.x * f01, v0.y * f00, v0.y * f01);
    float4 r1 = make_float4(v0.x * f10, v0.x * f11, v0.y * f10, v0.y * f11);
    float4 r2 = make_float4(v1.x * f00, v1.x * f01, v1.y * f00, v1.y * f01);
    float4 r3 = make_float4(v1.x * f10, v1.x * f11, v1.y * f10, v1.y * f11);

    __stcs(&o[0 * OUT_ROW_F4], r0);   // output row 4rp
    __stcs(&o[1 * OUT_ROW_F4], r1);   // output row 4rp+1
    __stcs(&o[2 * OUT_ROW_F4], r2);   // output row 4rp+2
    __stcs(&o[3 * OUT_ROW_F4], r3);   // output row 4rp+3
}

extern "C" void kernel_launch(void* const* d_in, const int* in_sizes, int n_in,
                              void* d_out, int out_size)
{
    const float2* x2  = (const float2*)d_in[0];   // [8,256,4,64,64] f32
    const float4* dw4 = (const float4*)d_in[1];   // [256,1,2,2] f32 -> one float4 per channel
    float4* out       = (float4*)d_out;           // [8,256,4,128,128] f32

    int nthreads = in_sizes[0] / 4;               // 8,388,608 (2 rows x float2 per thread)
    int block = 256;
    int grid  = (nthreads + block - 1) / block;   // 32768
    rre_up_kernel<<<grid, block>>>(x2, dw4, out, nthreads);
}

// round 6
// speedup vs baseline: 1.0136x; 1.0136x over previous
#include <cuda_runtime.h>
#include <cuda_bf16.h>

// DepthwiseRREUp: x [B=8, C=256, G=4, H=64, W=64] fp32, dw [C,1,2,2] fp32.
// out [B, C, G, 128, 128]:
//   out[b,c,g,2i+di,2j+dj] = x[b,c,g,i,j] * f(c,g)[di,dj],  f = rot90(dw[c], k=g) CCW.
//
// dw[c] = [[a,b],[c,d]] = (w.x, w.y, w.z, w.w):
//   g=0: f = (a,b,c,d)
//   g=1: f = (b,d,a,c)
//   g=2: f = (d,c,b,a)
//   g=3: f = (c,a,d,b)
// Note the cyclic structure: applying rot-90 once maps (f00,f01,f10,f11) ->
// (f01,f11,f00,f10). We compute g's permutation branch-free with two
// conditional swap stages (g&1: one rotation; g&2: two rotations = reverse).
//
// One thread per input FLOAT2. Each thread writes one float4 per output row
// (2 rows); consecutive lanes write consecutive float4 -> every STG.128 is
// fully lane-contiguous (full 32B sectors, minimal L1 wavefronts).

#define OUT_PLANE_F4 4096            // 128*128/4
#define OUT_ROW_F4   32              // 128/4

__global__ __launch_bounds__(512)
void rre_up_kernel(const float2* __restrict__ x2,
                   const float4* __restrict__ dw4,   // [C] float4 = (a,b,c,d)
                   float4* __restrict__ out)
{
    int idx = blockIdx.x * blockDim.x + threadIdx.x;   // exact grid, no tail

    int plane = idx >> 11;           // (b*C + c)*G + g, 0..8191
    int p     = idx & 2047;          // within-plane float2 index
    int i     = p >> 5;              // input row 0..63
    int j2    = p & 31;              // input float2 col == output float4 col

    int cg = plane & 1023;           // c*4 + g
    int c  = cg >> 2;
    int g  = cg & 3;

    float4 w = __ldg(&dw4[c]);       // warp-uniform broadcast, 4 KB total

    // Branch-free rot90 permutation.
    // Stage 1 (g&2 -> rotate twice == full reverse):
    float t00 = w.x, t01 = w.y, t10 = w.z, t11 = w.w;
    if (g & 2) { float a = t00, b = t01;
                 t00 = t11; t01 = t10; t10 = b; t11 = a; }
    // Stage 2 (g&1 -> rotate once: (f00,f01,f10,f11) <- (f01,f11,f00,f10)):
    float f00 = t00, f01 = t01, f10 = t10, f11 = t11;
    if (g & 1) { f00 = t01; f01 = t11; f10 = t00; f11 = t10; }

    float2 v = __ldcs(&x2[idx]);     // streamed read, no reuse

    float4* o = out + (size_t)plane * OUT_PLANE_F4
                    + (size_t)(2 * i) * OUT_ROW_F4
                    + j2;

    float4 r0 = make_float4(v.x * f00, v.x * f01, v.y * f00, v.y * f01);
    float4 r1 = make_float4(v.x * f10, v.x * f11, v.y * f10, v.y * f11);

    __stcs(&o[0],          r0);      // row 2i
    __stcs(&o[OUT_ROW_F4], r1);      // row 2i+1
}

extern "C" void kernel_launch(void* const* d_in, const int* in_sizes, int n_in,
                              void* d_out, int out_size)
{
    const float2* x2  = (const float2*)d_in[0];   // [8,256,4,64,64] f32
    const float4* dw4 = (const float4*)d_in[1];   // [256,1,2,2] f32
    float4* out       = (float4*)d_out;           // [8,256,4,128,128] f32

    int n2 = in_sizes[0] / 2;                     // 16,777,216 float2 (pow2: exact grid)
    int block = 512;
    int grid  = n2 / block;                       // 32768
    rre_up_kernel<<<grid, block>>>(x2, dw4, out);
}

// round 8
// speedup vs baseline: 1.0178x; 1.0041x over previous
#include <cuda_runtime.h>
#include <cuda_bf16.h>

// DepthwiseRREUp: x [B=8, C=256, G=4, H=64, W=64] fp32, dw [C,1,2,2] fp32.
// out [B, C, G, 128, 128]:
//   out[b,c,g,2i+di,2j+dj] = x[b,c,g,i,j] * f(c,g)[di,dj],  f = rot90(dw[c], k=g) CCW.
//
// dw[c] = [[a,b],[c,d]] = (w.x, w.y, w.z, w.w):
//   g=0: f = (a,b,c,d)   g=1: f = (b,d,a,c)   g=2: f = (d,c,b,a)   g=3: f = (c,a,d,b)
// Branch-free permutation: g&2 = double rotation (full reverse), g&1 = single
// rotation (f00,f01,f10,f11) <- (f01,f11,f00,f10).
//
// One thread per input FLOAT2; writes one fully lane-contiguous STG.128 per
// output row (2 rows). Stores use DEFAULT (evict-normal) policy: with 126 MB
// of L2, dirty output lines are drained by the writeback engine in large
// bursts instead of fine-grained evict-first interleaving with the read
// stream (testing the DRAM read/write-turnaround hypothesis).
// Reads stay __ldcs (read-once, keep them out of L2 residency).

#define OUT_PLANE_F4 4096            // 128*128/4
#define OUT_ROW_F4   32              // 128/4

__global__ __launch_bounds__(512)
void rre_up_kernel(const float2* __restrict__ x2,
                   const float4* __restrict__ dw4,   // [C] float4 = (a,b,c,d)
                   float4* __restrict__ out)
{
    int idx = blockIdx.x * blockDim.x + threadIdx.x;   // exact grid, no tail

    int plane = idx >> 11;           // (b*C + c)*G + g, 0..8191
    int p     = idx & 2047;          // within-plane float2 index
    int i     = p >> 5;              // input row 0..63
    int j2    = p & 31;              // input float2 col == output float4 col

    int cg = plane & 1023;           // c*4 + g
    int c  = cg >> 2;
    int g  = cg & 3;

    float4 w = __ldg(&dw4[c]);       // warp-uniform broadcast, 4 KB total

    // Branch-free rot90 permutation.
    float t00 = w.x, t01 = w.y, t10 = w.z, t11 = w.w;
    if (g & 2) { float a = t00, b = t01;
                 t00 = t11; t01 = t10; t10 = b; t11 = a; }
    float f00 = t00, f01 = t01, f10 = t10, f11 = t11;
    if (g & 1) { f00 = t01; f01 = t11; f10 = t00; f11 = t10; }

    float2 v = __ldcs(&x2[idx]);     // streamed read, no reuse

    float4* o = out + (size_t)plane * OUT_PLANE_F4
                    + (size_t)(2 * i) * OUT_ROW_F4
                    + j2;

    float4 r0 = make_float4(v.x * f00, v.x * f01, v.y * f00, v.y * f01);
    float4 r1 = make_float4(v.x * f10, v.x * f11, v.y * f10, v.y * f11);

    // Default evict-normal stores (NOT __stcs): let L2 batch the writebacks.
    o[0]          = r0;              // row 2i
    o[OUT_ROW_F4] = r1;              // row 2i+1
}

extern "C" void kernel_launch(void* const* d_in, const int* in_sizes, int n_in,
                              void* d_out, int out_size)
{
    const float2* x2  = (const float2*)d_in[0];   // [8,256,4,64,64] f32
    const float4* dw4 = (const float4*)d_in[1];   // [256,1,2,2] f32
    float4* out       = (float4*)d_out;           // [8,256,4,128,128] f32

    int n2 = in_sizes[0] / 2;                     // 16,777,216 float2 (pow2: exact grid)
    int block = 512;
    int grid  = n2 / block;                       // 32768
    rre_up_kernel<<<grid, block>>>(x2, dw4, out);
}

// round 10
// speedup vs baseline: 1.0188x; 1.0010x over previous
#include <cuda_runtime.h>
#include <cuda_bf16.h>

// DepthwiseRREUp: x [B=8, C=256, G=4, H=64, W=64] fp32, dw [C,1,2,2] fp32.
// out [B, C, G, 128, 128]:
//   out[b,c,g,2i+di,2j+dj] = x[b,c,g,i,j] * f(c,g)[di,dj],  f = rot90(dw[c], k=g) CCW.
//
// dw[c] = [[a,b],[c,d]] = (w.x, w.y, w.z, w.w):
//   g=0: f = (a,b,c,d)   g=1: f = (b,d,a,c)   g=2: f = (d,c,b,a)   g=3: f = (c,a,d,b)
// Branch-free permutation: g&2 = double rotation (reverse), g&1 = single
// rotation (f00,f01,f10,f11) <- (f01,f11,f00,f10).
//
// One thread per input FLOAT2; one fully lane-contiguous STG.128 per output
// row (2 rows). R9 experiment: WRITE-THROUGH stores (__stwt) — skip L2
// dirty-line allocate/writeback entirely; the store stream goes straight
// toward DRAM, so writebacks can't collide with the concurrent read stream.
// Reads stay __ldcs (read-once).

#define OUT_PLANE_F4 4096            // 128*128/4
#define OUT_ROW_F4   32              // 128/4

__global__ __launch_bounds__(512)
void rre_up_kernel(const float2* __restrict__ x2,
                   const float4* __restrict__ dw4,   // [C] float4 = (a,b,c,d)
                   float4* __restrict__ out)
{
    int idx = blockIdx.x * blockDim.x + threadIdx.x;   // exact grid, no tail

    int plane = idx >> 11;           // (b*C + c)*G + g, 0..8191
    int p     = idx & 2047;          // within-plane float2 index
    int i     = p >> 5;              // input row 0..63
    int j2    = p & 31;              // input float2 col == output float4 col

    int cg = plane & 1023;           // c*4 + g
    int c  = cg >> 2;
    int g  = cg & 3;

    float4 w = __ldg(&dw4[c]);       // warp-uniform broadcast, 4 KB total

    // Branch-free rot90 permutation.
    float t00 = w.x, t01 = w.y, t10 = w.z, t11 = w.w;
    if (g & 2) { float a = t00, b = t01;
                 t00 = t11; t01 = t10; t10 = b; t11 = a; }
    float f00 = t00, f01 = t01, f10 = t10, f11 = t11;
    if (g & 1) { f00 = t01; f01 = t11; f10 = t00; f11 = t10; }

    float2 v = __ldcs(&x2[idx]);     // streamed read, no reuse

    float4* o = out + (size_t)plane * OUT_PLANE_F4
                    + (size_t)(2 * i) * OUT_ROW_F4
                    + j2;

    float4 r0 = make_float4(v.x * f00, v.x * f01, v.y * f00, v.y * f01);
    float4 r1 = make_float4(v.x * f10, v.x * f11, v.y * f10, v.y * f11);

    __stwt(&o[0],          r0);      // row 2i   (write-through)
    __stwt(&o[OUT_ROW_F4], r1);      // row 2i+1 (write-through)
}

extern "C" void kernel_launch(void* const* d_in, const int* in_sizes, int n_in,
                              void* d_out, int out_size)
{
    const float2* x2  = (const float2*)d_in[0];   // [8,256,4,64,64] f32
    const float4* dw4 = (const float4*)d_in[1];   // [256,1,2,2] f32
    float4* out       = (float4*)d_out;           // [8,256,4,128,128] f32

    int n2 = in_sizes[0] / 2;                     // 16,777,216 float2 (pow2: exact grid)
    int block = 512;
    int grid  = n2 / block;                       // 32768
    rre_up_kernel<<<grid, block>>>(x2, dw4, out);
}